// round 2
// baseline (speedup 1.0000x reference)
#include <cuda_runtime.h>
#include <cuda_bf16.h>

typedef unsigned long long u64;

__device__ __forceinline__ u64 dup2(float v) {
    u64 r;
    asm("mov.b64 %0, {%1, %1};" : "=l"(r) : "f"(v));
    return r;
}
__device__ __forceinline__ void unpk(float& a, float& b, u64 p) {
    asm("mov.b64 {%0, %1}, %2;" : "=f"(a), "=f"(b) : "l"(p));
}
__device__ __forceinline__ void fma2(u64& d, u64 a, u64 b) {
    asm("fma.rn.f32x2 %0, %1, %2, %0;" : "+l"(d) : "l"(a), "l"(b));
}

#define NROWS 200000
#define NTILES 3125          // 200000 / 64
#define BM 64
#define LDIM 480

// ---------------------------------------------------------------------------
// Kernel 0: out[:, 0:128] = x[:, 0:128] @ (a0*w0) + b0
// smem: w0s[128][128] + b0s[128] + xs[64][132]  (99840 B) -> 2 CTAs/SM
// map: cg = tid>>4 (16 col-groups x 8 cols), rg = tid&15 (16 row-groups x 4 rows)
// All LDS.64 on xs use even float offsets (k steps by 2) -> 8B aligned.
// ---------------------------------------------------------------------------
__global__ void __launch_bounds__(256, 2)
k0_kernel(const float* __restrict__ x, const float* __restrict__ w0,
          const float* __restrict__ b0, float* __restrict__ out)
{
    extern __shared__ float smem[];
    float* w0s = smem;                 // 16384
    float* b0s = w0s + 128 * 128;      // 128
    float* xs  = b0s + 128;            // 64*132

    const int tid = threadIdx.x;
    const float a0 = 0.08838834764831845f;  // 1/sqrt(128)

    #pragma unroll
    for (int i = tid; i < 4096; i += 256) {
        float4 v = ((const float4*)w0)[i];
        v.x *= a0; v.y *= a0; v.z *= a0; v.w *= a0;
        ((float4*)w0s)[i] = v;
    }
    if (tid < 128) b0s[tid] = b0[tid];

    const int cg = tid >> 4;    // 0..15
    const int rg = tid & 15;    // 0..15
    const int c0 = cg * 8;

    for (int tile = blockIdx.x; tile < NTILES; tile += gridDim.x) {
        const int row0 = tile * BM;
        __syncthreads();
        #pragma unroll
        for (int i = tid; i < 64 * 32; i += 256) {
            int r = i >> 5, c4 = (i & 31) << 2;
            float4 v = *(const float4*)(x + (row0 + r) * LDIM + c4);
            *(float4*)(xs + r * 132 + c4) = v;
        }
        __syncthreads();

        u64 acc[4][4];
        #pragma unroll
        for (int ri = 0; ri < 4; ri++) {
            #pragma unroll
            for (int p = 0; p < 4; p++) {
                u64 t;
                asm("mov.b64 %0, {%1, %2};" : "=l"(t)
                    : "f"(b0s[c0 + 2 * p]), "f"(b0s[c0 + 2 * p + 1]));
                acc[ri][p] = t;
            }
        }

        #pragma unroll 4
        for (int k = 0; k < 128; k += 2) {
            ulonglong2 wa  = *(const ulonglong2*)(w0s + k * 128 + c0);
            ulonglong2 wb  = *(const ulonglong2*)(w0s + k * 128 + c0 + 4);
            ulonglong2 wa1 = *(const ulonglong2*)(w0s + (k + 1) * 128 + c0);
            ulonglong2 wb1 = *(const ulonglong2*)(w0s + (k + 1) * 128 + c0 + 4);
            #pragma unroll
            for (int ri = 0; ri < 4; ri++) {
                const int r = rg + 16 * ri;
                u64 xp = *(const u64*)(xs + r * 132 + k);
                float xl, xh;
                unpk(xl, xh, xp);
                u64 xa = dup2(xl), xb = dup2(xh);
                fma2(acc[ri][0], xa, wa.x);
                fma2(acc[ri][1], xa, wa.y);
                fma2(acc[ri][2], xa, wb.x);
                fma2(acc[ri][3], xa, wb.y);
                fma2(acc[ri][0], xb, wa1.x);
                fma2(acc[ri][1], xb, wa1.y);
                fma2(acc[ri][2], xb, wb1.x);
                fma2(acc[ri][3], xb, wb1.y);
            }
        }

        #pragma unroll
        for (int ri = 0; ri < 4; ri++) {
            const int r = rg + 16 * ri;
            float* o = out + (row0 + r) * LDIM + c0;
            *(ulonglong2*)o       = make_ulonglong2(acc[ri][0], acc[ri][1]);
            *(ulonglong2*)(o + 4) = make_ulonglong2(acc[ri][2], acc[ri][3]);
        }
    }
}

// ---------------------------------------------------------------------------
// Kernel 1: out[:, 128+3w+i] = sum_u x[:, 128+3u+i] * a1*w1[u,w]   (i=0..2)
// TRANSPOSED x tile: xs1t[192][66] (column-major, row pad 66), so f32x2 packs
// along ROW PAIRS -> direct aligned LDS.64, zero packing movs on the x side.
// smem: w1s[64][64] + xs1t[192][66]  (67072 B) -> 3 CTAs/SM
// map: cg = tid>>5 (8 col-groups x 8 w-cols), rg = tid&31 (row pair 2rg,2rg+1)
// ---------------------------------------------------------------------------
__global__ void __launch_bounds__(256, 3)
k1_kernel(const float* __restrict__ x, const float* __restrict__ w1,
          float* __restrict__ out)
{
    extern __shared__ float smem[];
    float* w1s  = smem;                // 4096
    float* xs1t = w1s + 64 * 64;       // 192*66

    const int tid = threadIdx.x;
    const float a1 = 0.125f;           // 1/sqrt(64)

    #pragma unroll
    for (int i = tid; i < 1024; i += 256) {
        float4 v = ((const float4*)w1)[i];
        v.x *= a1; v.y *= a1; v.z *= a1; v.w *= a1;
        ((float4*)w1s)[i] = v;
    }

    const int cg = tid >> 5;   // 0..7 (warp-uniform)
    const int rg = tid & 31;   // 0..31
    const int w0c = cg * 8;

    for (int tile = blockIdx.x; tile < NTILES; tile += gridDim.x) {
        const int row0 = tile * BM;
        __syncthreads();
        // transpose-load x tile: xs1t[c][r], c = 0..191, r = 0..63
        #pragma unroll 4
        for (int i = tid; i < 64 * 192; i += 256) {
            int r = i / 192, c = i - r * 192;
            xs1t[c * 66 + r] = x[(row0 + r) * LDIM + 128 + c];
        }
        __syncthreads();

        u64 C[3][8];   // [i][wj] packs rows (2rg, 2rg+1)
        #pragma unroll
        for (int ii = 0; ii < 3; ii++)
            #pragma unroll
            for (int j = 0; j < 8; j++) C[ii][j] = 0ULL;

        #pragma unroll 2
        for (int k = 0; k < 64; k++) {
            float4 wv0 = *(const float4*)(w1s + k * 64 + w0c);
            float4 wv1 = *(const float4*)(w1s + k * 64 + w0c + 4);
            u64 x0 = *(const u64*)(xs1t + (3 * k + 0) * 66 + 2 * rg);
            u64 x1 = *(const u64*)(xs1t + (3 * k + 1) * 66 + 2 * rg);
            u64 x2 = *(const u64*)(xs1t + (3 * k + 2) * 66 + 2 * rg);
            u64 d;
            d = dup2(wv0.x); fma2(C[0][0], x0, d); fma2(C[1][0], x1, d); fma2(C[2][0], x2, d);
            d = dup2(wv0.y); fma2(C[0][1], x0, d); fma2(C[1][1], x1, d); fma2(C[2][1], x2, d);
            d = dup2(wv0.z); fma2(C[0][2], x0, d); fma2(C[1][2], x1, d); fma2(C[2][2], x2, d);
            d = dup2(wv0.w); fma2(C[0][3], x0, d); fma2(C[1][3], x1, d); fma2(C[2][3], x2, d);
            d = dup2(wv1.x); fma2(C[0][4], x0, d); fma2(C[1][4], x1, d); fma2(C[2][4], x2, d);
            d = dup2(wv1.y); fma2(C[0][5], x0, d); fma2(C[1][5], x1, d); fma2(C[2][5], x2, d);
            d = dup2(wv1.z); fma2(C[0][6], x0, d); fma2(C[1][6], x1, d); fma2(C[2][6], x2, d);
            d = dup2(wv1.w); fma2(C[0][7], x0, d); fma2(C[1][7], x1, d); fma2(C[2][7], x2, d);
        }

        // rows row0+2rg, row0+2rg+1; 24 contiguous output cols at 128+24cg
        float vA[24], vB[24];
        #pragma unroll
        for (int ii = 0; ii < 3; ii++)
            #pragma unroll
            for (int j = 0; j < 8; j++)
                unpk(vA[3 * j + ii], vB[3 * j + ii], C[ii][j]);

        float* oA = out + (row0 + 2 * rg) * LDIM + 128 + 24 * cg;
        float* oB = oA + LDIM;
        #pragma unroll
        for (int q = 0; q < 6; q++) {
            *(float4*)(oA + 4 * q) = make_float4(vA[4 * q], vA[4 * q + 1], vA[4 * q + 2], vA[4 * q + 3]);
            *(float4*)(oB + 4 * q) = make_float4(vB[4 * q], vB[4 * q + 1], vB[4 * q + 2], vB[4 * q + 3]);
        }
    }
}

// ---------------------------------------------------------------------------
// Kernel 2: out[:, 320+5w+i] = sum_u x[:, 320+5u+i] * a2*w2[u,w]   (i=0..4)
// smem: w2s[32][32] + xs2t[160][66] transposed (46336 B) -> 4 CTAs/SM
// map: cg = tid>>5 (8 col-groups x 4 w-cols), rg = tid&31 (row pair 2rg,2rg+1)
// ---------------------------------------------------------------------------
__global__ void __launch_bounds__(256, 4)
k2_kernel(const float* __restrict__ x, const float* __restrict__ w2,
          float* __restrict__ out)
{
    extern __shared__ float smem[];
    float* w2s  = smem;                 // 1024
    float* xs2t = w2s + 32 * 32;        // 160 * 66

    const int tid = threadIdx.x;
    const float a2 = 0.17677669529663687f;  // 1/sqrt(32)

    #pragma unroll
    for (int i = tid; i < 256; i += 256) {
        float4 v = ((const float4*)w2)[i];
        v.x *= a2; v.y *= a2; v.z *= a2; v.w *= a2;
        ((float4*)w2s)[i] = v;
    }

    const int cg = tid >> 5;   // 0..7 (warp-uniform)
    const int rg = tid & 31;   // 0..31
    const int w0c = cg * 4;

    for (int tile = blockIdx.x; tile < NTILES; tile += gridDim.x) {
        const int row0 = tile * BM;
        __syncthreads();
        #pragma unroll 4
        for (int i = tid; i < 64 * 160; i += 256) {
            int r = i / 160, c = i - r * 160;
            xs2t[c * 66 + r] = x[(row0 + r) * LDIM + 320 + c];
        }
        __syncthreads();

        u64 C[5][4];
        #pragma unroll
        for (int ii = 0; ii < 5; ii++)
            #pragma unroll
            for (int j = 0; j < 4; j++) C[ii][j] = 0ULL;

        #pragma unroll 4
        for (int k = 0; k < 32; k++) {
            float4 wv = *(const float4*)(w2s + k * 32 + w0c);
            u64 dw0 = dup2(wv.x), dw1 = dup2(wv.y), dw2 = dup2(wv.z), dw3 = dup2(wv.w);
            #pragma unroll
            for (int ii = 0; ii < 5; ii++) {
                u64 xp = *(const u64*)(xs2t + (5 * k + ii) * 66 + 2 * rg);
                fma2(C[ii][0], xp, dw0);
                fma2(C[ii][1], xp, dw1);
                fma2(C[ii][2], xp, dw2);
                fma2(C[ii][3], xp, dw3);
            }
        }

        float vA[20], vB[20];
        #pragma unroll
        for (int ii = 0; ii < 5; ii++)
            #pragma unroll
            for (int j = 0; j < 4; j++)
                unpk(vA[5 * j + ii], vB[5 * j + ii], C[ii][j]);

        float* oA = out + (row0 + 2 * rg) * LDIM + 320 + 20 * cg;
        float* oB = oA + LDIM;
        #pragma unroll
        for (int q = 0; q < 5; q++) {
            *(float4*)(oA + 4 * q) = make_float4(vA[4 * q], vA[4 * q + 1], vA[4 * q + 2], vA[4 * q + 3]);
            *(float4*)(oB + 4 * q) = make_float4(vB[4 * q], vB[4 * q + 1], vB[4 * q + 2], vB[4 * q + 3]);
        }
    }
}

// ---------------------------------------------------------------------------

extern "C" void kernel_launch(void* const* d_in, const int* in_sizes, int n_in,
                              void* d_out, int out_size)
{
    const float* x  = (const float*)d_in[0];
    const float* w0 = (const float*)d_in[1];
    const float* w1 = (const float*)d_in[2];
    const float* w2 = (const float*)d_in[3];
    const float* b0 = (const float*)d_in[4];
    float* out = (float*)d_out;

    const int smem0 = (128 * 128 + 128 + 64 * 132) * 4;   // 99840
    const int smem1 = (64 * 64 + 192 * 66) * 4;           // 67072
    const int smem2 = (32 * 32 + 160 * 66) * 4;           // 46336

    cudaFuncSetAttribute(k0_kernel, cudaFuncAttributeMaxDynamicSharedMemorySize, smem0);
    cudaFuncSetAttribute(k1_kernel, cudaFuncAttributeMaxDynamicSharedMemorySize, smem1);
    cudaFuncSetAttribute(k2_kernel, cudaFuncAttributeMaxDynamicSharedMemorySize, smem2);

    k0_kernel<<<304, 256, smem0>>>(x, w0, b0, out);
    k1_kernel<<<456, 256, smem1>>>(x, w1, out);
    k2_kernel<<<608, 256, smem2>>>(x, w2, out);
}

// round 4
// speedup vs baseline: 1.2161x; 1.2161x over previous
#include <cuda_runtime.h>
#include <cuda_bf16.h>
#include <cstdint>

typedef unsigned long long u64;

// f32x2 helpers for FFMA2 kernels (k1/k2)
__device__ __forceinline__ u64 dup2(float v) {
    u64 r; asm("mov.b64 %0, {%1, %1};" : "=l"(r) : "f"(v)); return r;
}
__device__ __forceinline__ void unpk(float& a, float& b, u64 p) {
    asm("mov.b64 {%0, %1}, %2;" : "=f"(a), "=f"(b) : "l"(p));
}
__device__ __forceinline__ void fma2(u64& d, u64 a, u64 b) {
    asm("fma.rn.f32x2 %0, %1, %2, %0;" : "+l"(d) : "l"(a), "l"(b));
}

#define NROWS 200000
#define NTILES 3125          // 200000 / 64
#define BM 64
#define LDIM 480

// ============================================================================
// Kernel 0 (HMMA): out[:, 0:128] = x[:, 0:128] @ (a0*w0) + b0
// mma.sync.aligned.m16n8k16 bf16, hi/lo 3-pass split (AhBh + AlBh + AhBl).
// smem (bytes): b0s[0,512) Bh[512,35328) Bl[35328,70144)
//               Ah[70144,87552) Al[87552,104960)   -> 2 CTAs/SM
// bf16 row stride 136 -> fragment lds bank = (4*row + kp) mod 32: conflict-free.
// 8 warps = 4 m-tiles (16 rows) x 2 n-halves (64 cols).
// ============================================================================
#define K0_STRIDE 136
#define K0_B0   0
#define K0_BH   512
#define K0_BL   35328
#define K0_AH   70144
#define K0_AL   87552
#define K0_SMEM 104960

__device__ __forceinline__ void mma_bf16(float& c0, float& c1, float& c2, float& c3,
                                         uint32_t a0, uint32_t a1, uint32_t a2, uint32_t a3,
                                         uint32_t b0, uint32_t b1)
{
    asm volatile("mma.sync.aligned.m16n8k16.row.col.f32.bf16.bf16.f32 "
                 "{%0,%1,%2,%3}, {%4,%5,%6,%7}, {%8,%9}, {%0,%1,%2,%3};"
                 : "+f"(c0), "+f"(c1), "+f"(c2), "+f"(c3)
                 : "r"(a0), "r"(a1), "r"(a2), "r"(a3), "r"(b0), "r"(b1));
}

__device__ __forceinline__ uint32_t pack_hi(float x, float y, float& rx, float& ry) {
    __nv_bfloat162 h = __float22bfloat162_rn(make_float2(x, y));
    float2 hf = __bfloat1622float2(h);
    rx = x - hf.x; ry = y - hf.y;
    return *(uint32_t*)&h;
}
__device__ __forceinline__ uint32_t pack_lo(float rx, float ry) {
    __nv_bfloat162 l = __float22bfloat162_rn(make_float2(rx, ry));
    return *(uint32_t*)&l;
}

__global__ void __launch_bounds__(256, 2)
k0_mma(const float* __restrict__ x, const float* __restrict__ w0,
       const float* __restrict__ b0, float* __restrict__ out)
{
    extern __shared__ char smem[];
    float* b0s = (float*)(smem + K0_B0);

    const int tid  = threadIdx.x;
    const int wid  = tid >> 5;
    const int lane = tid & 31;
    const float a0 = 0.08838834764831845f;   // 1/sqrt(128)

    // ---- stage weights: B[n][k] = a0 * w0[k][n], hi/lo bf16, stride 136 ----
    for (int idx = tid; idx < 128 * 128; idx += 256) {
        int n = idx & 127, k = idx >> 7;          // n fast -> coalesced w0 reads
        float v = a0 * w0[k * 128 + n];
        float r0, r1;
        // scalar pack via vector helper (second slot dummy)
        __nv_bfloat16 h = __float2bfloat16(v);
        float r = v - __bfloat162float(h);
        __nv_bfloat16 l = __float2bfloat16(r);
        (void)r0; (void)r1;
        *(__nv_bfloat16*)(smem + K0_BH + (n * K0_STRIDE + k) * 2) = h;
        *(__nv_bfloat16*)(smem + K0_BL + (n * K0_STRIDE + k) * 2) = l;
    }
    if (tid < 128) b0s[tid] = b0[tid];

    const int mt = wid >> 1;        // m-tile 0..3 (16 rows each)
    const int nh = wid & 1;         // n-half 0..1 (64 cols each)
    const int ar = mt * 16 + (lane >> 2);   // A fragment row (0..63)
    const int ak = (lane & 3) * 2;          // A fragment k base
    const int bn = nh * 64 + (lane >> 2);   // B fragment n base (+nt*8)
    const int ncol = nh * 64 + (lane & 3) * 2;

    __syncthreads();

    for (int t = blockIdx.x; t < NTILES; t += gridDim.x) {
        const int row0 = t * BM;

        // ---- stage x tile -> Ah/Al (64 rows x 128 k), stride 136 ----
        #pragma unroll
        for (int i = tid; i < 64 * 32; i += 256) {
            int r = i >> 5, c4 = (i & 31) << 2;
            float4 v = *(const float4*)(x + (size_t)(row0 + r) * LDIM + c4);
            float rx, ry, rz, rw;
            uint32_t h0 = pack_hi(v.x, v.y, rx, ry);
            uint32_t h1 = pack_hi(v.z, v.w, rz, rw);
            uint32_t l0 = pack_lo(rx, ry);
            uint32_t l1 = pack_lo(rz, rw);
            uint32_t off = (uint32_t)(r * K0_STRIDE + c4) * 2u;
            *(uint2*)(smem + K0_AH + off) = make_uint2(h0, h1);
            *(uint2*)(smem + K0_AL + off) = make_uint2(l0, l1);
        }
        __syncthreads();

        // ---- load A fragments into registers (held across all n-tiles) ----
        uint32_t ah[8][4], al[8][4];
        {
            const uint32_t base = (uint32_t)(ar * K0_STRIDE + ak) * 2u;
            #pragma unroll
            for (int ks = 0; ks < 8; ks++) {
                uint32_t o = base + (uint32_t)(ks * 16) * 2u;
                ah[ks][0] = *(const uint32_t*)(smem + K0_AH + o);
                ah[ks][1] = *(const uint32_t*)(smem + K0_AH + o + 8 * K0_STRIDE * 2);
                ah[ks][2] = *(const uint32_t*)(smem + K0_AH + o + 16);
                ah[ks][3] = *(const uint32_t*)(smem + K0_AH + o + 8 * K0_STRIDE * 2 + 16);
                al[ks][0] = *(const uint32_t*)(smem + K0_AL + o);
                al[ks][1] = *(const uint32_t*)(smem + K0_AL + o + 8 * K0_STRIDE * 2);
                al[ks][2] = *(const uint32_t*)(smem + K0_AL + o + 16);
                al[ks][3] = *(const uint32_t*)(smem + K0_AL + o + 8 * K0_STRIDE * 2 + 16);
            }
        }

        // ---- per n-tile: 8 k-steps x 3 passes ----
        #pragma unroll
        for (int nt = 0; nt < 8; nt++) {
            float c0 = b0s[ncol + nt * 8];
            float c1 = b0s[ncol + nt * 8 + 1];
            float c2 = c0, c3 = c1;
            const uint32_t bbase = (uint32_t)((bn + nt * 8) * K0_STRIDE + ak) * 2u;
            #pragma unroll
            for (int ks = 0; ks < 8; ks++) {
                uint32_t o = bbase + (uint32_t)(ks * 16) * 2u;
                uint32_t bh0 = *(const uint32_t*)(smem + K0_BH + o);
                uint32_t bh1 = *(const uint32_t*)(smem + K0_BH + o + 16);
                uint32_t bl0 = *(const uint32_t*)(smem + K0_BL + o);
                uint32_t bl1 = *(const uint32_t*)(smem + K0_BL + o + 16);
                mma_bf16(c0, c1, c2, c3, ah[ks][0], ah[ks][1], ah[ks][2], ah[ks][3], bh0, bh1);
                mma_bf16(c0, c1, c2, c3, al[ks][0], al[ks][1], al[ks][2], al[ks][3], bh0, bh1);
                mma_bf16(c0, c1, c2, c3, ah[ks][0], ah[ks][1], ah[ks][2], ah[ks][3], bl0, bl1);
            }
            const int grow = row0 + mt * 16 + (lane >> 2);
            float* o0 = out + (size_t)grow * LDIM + ncol + nt * 8;
            *(float2*)o0              = make_float2(c0, c1);
            *(float2*)(o0 + 8 * LDIM) = make_float2(c2, c3);
        }
        __syncthreads();   // protect Ah/Al before next tile's staging
    }
}

// ============================================================================
// Kernel 1 (FFMA2, unchanged from passing R2): out[:, 128+3w+i]
// ============================================================================
__global__ void __launch_bounds__(256, 3)
k1_kernel(const float* __restrict__ x, const float* __restrict__ w1,
          float* __restrict__ out)
{
    extern __shared__ float smemf[];
    float* w1s  = smemf;               // 4096
    float* xs1t = w1s + 64 * 64;       // 192*66

    const int tid = threadIdx.x;
    const float a1 = 0.125f;

    #pragma unroll
    for (int i = tid; i < 1024; i += 256) {
        float4 v = ((const float4*)w1)[i];
        v.x *= a1; v.y *= a1; v.z *= a1; v.w *= a1;
        ((float4*)w1s)[i] = v;
    }

    const int cg = tid >> 5;
    const int rg = tid & 31;
    const int w0c = cg * 8;

    for (int tile = blockIdx.x; tile < NTILES; tile += gridDim.x) {
        const int row0 = tile * BM;
        __syncthreads();
        #pragma unroll 4
        for (int i = tid; i < 64 * 192; i += 256) {
            int r = i / 192, c = i - r * 192;
            xs1t[c * 66 + r] = x[(row0 + r) * LDIM + 128 + c];
        }
        __syncthreads();

        u64 C[3][8];
        #pragma unroll
        for (int ii = 0; ii < 3; ii++)
            #pragma unroll
            for (int j = 0; j < 8; j++) C[ii][j] = 0ULL;

        #pragma unroll 2
        for (int k = 0; k < 64; k++) {
            float4 wv0 = *(const float4*)(w1s + k * 64 + w0c);
            float4 wv1 = *(const float4*)(w1s + k * 64 + w0c + 4);
            u64 x0 = *(const u64*)(xs1t + (3 * k + 0) * 66 + 2 * rg);
            u64 x1 = *(const u64*)(xs1t + (3 * k + 1) * 66 + 2 * rg);
            u64 x2 = *(const u64*)(xs1t + (3 * k + 2) * 66 + 2 * rg);
            u64 d;
            d = dup2(wv0.x); fma2(C[0][0], x0, d); fma2(C[1][0], x1, d); fma2(C[2][0], x2, d);
            d = dup2(wv0.y); fma2(C[0][1], x0, d); fma2(C[1][1], x1, d); fma2(C[2][1], x2, d);
            d = dup2(wv0.z); fma2(C[0][2], x0, d); fma2(C[1][2], x1, d); fma2(C[2][2], x2, d);
            d = dup2(wv0.w); fma2(C[0][3], x0, d); fma2(C[1][3], x1, d); fma2(C[2][3], x2, d);
            d = dup2(wv1.x); fma2(C[0][4], x0, d); fma2(C[1][4], x1, d); fma2(C[2][4], x2, d);
            d = dup2(wv1.y); fma2(C[0][5], x0, d); fma2(C[1][5], x1, d); fma2(C[2][5], x2, d);
            d = dup2(wv1.z); fma2(C[0][6], x0, d); fma2(C[1][6], x1, d); fma2(C[2][6], x2, d);
            d = dup2(wv1.w); fma2(C[0][7], x0, d); fma2(C[1][7], x1, d); fma2(C[2][7], x2, d);
        }

        float vA[24], vB[24];
        #pragma unroll
        for (int ii = 0; ii < 3; ii++)
            #pragma unroll
            for (int j = 0; j < 8; j++)
                unpk(vA[3 * j + ii], vB[3 * j + ii], C[ii][j]);

        float* oA = out + (row0 + 2 * rg) * LDIM + 128 + 24 * cg;
        float* oB = oA + LDIM;
        #pragma unroll
        for (int q = 0; q < 6; q++) {
            *(float4*)(oA + 4 * q) = make_float4(vA[4 * q], vA[4 * q + 1], vA[4 * q + 2], vA[4 * q + 3]);
            *(float4*)(oB + 4 * q) = make_float4(vB[4 * q], vB[4 * q + 1], vB[4 * q + 2], vB[4 * q + 3]);
        }
    }
}

// ============================================================================
// Kernel 2 (FFMA2, unchanged from passing R2): out[:, 320+5w+i]
// ============================================================================
__global__ void __launch_bounds__(256, 4)
k2_kernel(const float* __restrict__ x, const float* __restrict__ w2,
          float* __restrict__ out)
{
    extern __shared__ float smemf[];
    float* w2s  = smemf;                // 1024
    float* xs2t = w2s + 32 * 32;        // 160 * 66

    const int tid = threadIdx.x;
    const float a2 = 0.17677669529663687f;

    #pragma unroll
    for (int i = tid; i < 256; i += 256) {
        float4 v = ((const float4*)w2)[i];
        v.x *= a2; v.y *= a2; v.z *= a2; v.w *= a2;
        ((float4*)w2s)[i] = v;
    }

    const int cg = tid >> 5;
    const int rg = tid & 31;
    const int w0c = cg * 4;

    for (int tile = blockIdx.x; tile < NTILES; tile += gridDim.x) {
        const int row0 = tile * BM;
        __syncthreads();
        #pragma unroll 4
        for (int i = tid; i < 64 * 160; i += 256) {
            int r = i / 160, c = i - r * 160;
            xs2t[c * 66 + r] = x[(row0 + r) * LDIM + 320 + c];
        }
        __syncthreads();

        u64 C[5][4];
        #pragma unroll
        for (int ii = 0; ii < 5; ii++)
            #pragma unroll
            for (int j = 0; j < 4; j++) C[ii][j] = 0ULL;

        #pragma unroll 4
        for (int k = 0; k < 32; k++) {
            float4 wv = *(const float4*)(w2s + k * 32 + w0c);
            u64 dw0 = dup2(wv.x), dw1 = dup2(wv.y), dw2 = dup2(wv.z), dw3 = dup2(wv.w);
            #pragma unroll
            for (int ii = 0; ii < 5; ii++) {
                u64 xp = *(const u64*)(xs2t + (5 * k + ii) * 66 + 2 * rg);
                fma2(C[ii][0], xp, dw0);
                fma2(C[ii][1], xp, dw1);
                fma2(C[ii][2], xp, dw2);
                fma2(C[ii][3], xp, dw3);
            }
        }

        float vA[20], vB[20];
        #pragma unroll
        for (int ii = 0; ii < 5; ii++)
            #pragma unroll
            for (int j = 0; j < 4; j++)
                unpk(vA[5 * j + ii], vB[5 * j + ii], C[ii][j]);

        float* oA = out + (row0 + 2 * rg) * LDIM + 320 + 20 * cg;
        float* oB = oA + LDIM;
        #pragma unroll
        for (int q = 0; q < 5; q++) {
            *(float4*)(oA + 4 * q) = make_float4(vA[4 * q], vA[4 * q + 1], vA[4 * q + 2], vA[4 * q + 3]);
            *(float4*)(oB + 4 * q) = make_float4(vB[4 * q], vB[4 * q + 1], vB[4 * q + 2], vB[4 * q + 3]);
        }
    }
}

// ============================================================================

extern "C" void kernel_launch(void* const* d_in, const int* in_sizes, int n_in,
                              void* d_out, int out_size)
{
    const float* x  = (const float*)d_in[0];
    const float* w0 = (const float*)d_in[1];
    const float* w1 = (const float*)d_in[2];
    const float* w2 = (const float*)d_in[3];
    const float* b0 = (const float*)d_in[4];
    float* out = (float*)d_out;

    const int smem1 = (64 * 64 + 192 * 66) * 4;           // 67072
    const int smem2 = (32 * 32 + 160 * 66) * 4;           // 46336

    cudaFuncSetAttribute(k0_mma, cudaFuncAttributeMaxDynamicSharedMemorySize, K0_SMEM);
    cudaFuncSetAttribute(k1_kernel, cudaFuncAttributeMaxDynamicSharedMemorySize, smem1);
    cudaFuncSetAttribute(k2_kernel, cudaFuncAttributeMaxDynamicSharedMemorySize, smem2);

    k0_mma<<<304, 256, K0_SMEM>>>(x, w0, b0, out);
    k1_kernel<<<456, 256, smem1>>>(x, w1, out);
    k2_kernel<<<608, 256, smem2>>>(x, w2, out);
}